// round 7
// baseline (speedup 1.0000x reference)
#include <cuda_runtime.h>
#include <cuda_fp16.h>
#include <cstdint>

// Problem constants (fixed by the dataset)
#define N0C 10000
#define N1C 40000
#define N2C 160000
#define E1C 240000
#define E2C 960000

// Static scratch (no allocation allowed)
__device__ __half g_Z[N2C * 9 * 16];               // 46.1 MB (>= N1C*9*32 halves)
__device__ float g_bufA[N2C * 32];                 // 20.5 MB
__device__ float g_bufB[N2C * 32];                 // 20.5 MB
// B-operand packed in exact mma.m16n8k16 fragment order (uint32 = 2 halves)
__device__ unsigned int g_Bp[19200];
#define BP_1A 0        // 320/8 * 4ks * 64 = 10240
#define BP_2A 10240    // 320/8 * 2ks * 64 = 5120
#define BP_1B 15360    // 160/8 * 2ks * 64 = 2560
#define BP_2B 17920    // 160/8 * 1ks * 64 = 1280

// ===========================================================================
// Pack B fragments: Wt[j][k] (j = output col of [W|R] concat, k = input chan)
//   j  = nt*8 + (lane>>2)
//   kb = ks*16 + (lane&3)*2 + r*8   -> halves (kb, kb+1)
// ===========================================================================
__device__ __forceinline__ float wt_val(const float* __restrict__ W,
                                        const float* __restrict__ R,
                                        int CIN, int COUT, int j, int k) {
    if (j < 9 * COUT) {
        int kk = j / COUT;
        int co = j - kk * COUT;
        return W[((size_t)kk * CIN + k) * COUT + co];
    }
    return R[(size_t)k * COUT + (j - 9 * COUT)];
}

__device__ __forceinline__ void pack_b_one(const float* __restrict__ W,
                                           const float* __restrict__ R,
                                           int CIN, int COUT,
                                           unsigned int* __restrict__ Bp, int u) {
    int r = u & 1;
    int lane = (u >> 1) & 31;
    int rest = u >> 6;
    int KS = CIN / 16;
    int ks = rest % KS;
    int nt = rest / KS;
    int j = nt * 8 + (lane >> 2);
    int kb = ks * 16 + (lane & 3) * 2 + r * 8;
    __half2 h = __floats2half2_rn(wt_val(W, R, CIN, COUT, j, kb),
                                  wt_val(W, R, CIN, COUT, j, kb + 1));
    Bp[u] = *reinterpret_cast<unsigned int*>(&h);
}

__global__ void pack_all_kernel(const float* W1a, const float* R1a,
                                const float* W2a, const float* R2a,
                                const float* W1b, const float* R1b,
                                const float* W2b, const float* R2b,
                                unsigned int* __restrict__ Bp) {
    int i = blockIdx.x * blockDim.x + threadIdx.x;
    if (i < 10240)       pack_b_one(W1a, R1a, 64, 32, Bp + BP_1A, i);
    else if (i < 15360)  pack_b_one(W2a, R2a, 32, 32, Bp + BP_2A, i - 10240);
    else if (i < 17920)  pack_b_one(W1b, R1b, 32, 16, Bp + BP_1B, i - 15360);
    else if (i < 19200)  pack_b_one(W2b, R2b, 16, 16, Bp + BP_2B, i - 17920);
}

// ===========================================================================
// HMMA node kernel: 128 nodes/block, 8 warps (2 M-groups x 4 N-groups),
// looping over 4 M-chunks of 32 nodes; B staged in smem ONCE per block.
//   Z[n, 0:9*COUT] (fp16) = X[n,:] @ Wcat ; O[n,:] = X[n,:] @ R + b (fp32)
// ===========================================================================
template <int CIN, int COUT>
__global__ void __launch_bounds__(256)
node_mma_kernel(const float* __restrict__ xA, int CA,
                const float* __restrict__ xB,
                const int* __restrict__ gidx, int reluA,
                const unsigned int* __restrict__ Bp,
                const float* __restrict__ bias,
                __half* __restrict__ Z, float* __restrict__ O, int N) {
    constexpr int KS = CIN / 16;
    constexpr int NOUT = 10 * COUT;
    constexpr int NT_TOT = NOUT / 8;
    constexpr int NTW = NT_TOT / 4;        // tiles per warp (10 or 5)
    constexpr int ZW = 9 * COUT;
    constexpr int SA = CIN + 8;            // padded smem stride (halves)
    constexpr int BP_SZ = NT_TOT * KS * 64;

    extern __shared__ char smem[];
    __half* As = reinterpret_cast<__half*>(smem);                 // 128*SA
    unsigned int* Bs = reinterpret_cast<unsigned int*>(smem + 128 * SA * 2);
    int* rows = reinterpret_cast<int*>(smem + 128 * SA * 2 + BP_SZ * 4);

    int tid = threadIdx.x;
    int lane = tid & 31;
    int wid = tid >> 5;
    int mg = wid >> 2;                     // 0..1 M group
    int ng = wid & 3;                      // 0..3 N group
    int g = lane >> 2;                     // 0..7
    int tig = lane & 3;                    // 0..3
    int nodeBase = blockIdx.x * 128;

    if (tid < 128) {
        int n = nodeBase + tid;
        rows[tid] = (n < N) ? (gidx ? gidx[n] : n) : 0;
    }
    __syncthreads();

    // ---- gather X rows -> fp16 smem (half2 granularity) ----
    for (int i = tid; i < 128 * (CIN / 2); i += 256) {
        int row = i / (CIN / 2);
        int col = (i - row * (CIN / 2)) * 2;
        int r = rows[row];
        float2 v;
        if (col < CA) {
            v = *reinterpret_cast<const float2*>(xA + (size_t)r * CA + col);
            if (reluA) { v.x = fmaxf(v.x, 0.f); v.y = fmaxf(v.y, 0.f); }
        } else {
            v = *reinterpret_cast<const float2*>(
                    xB + (size_t)r * (CIN - CA) + (col - CA));
        }
        __half2 h = __floats2half2_rn(v.x, v.y);
        *reinterpret_cast<__half2*>(&As[row * SA + col]) = h;
    }
    // ---- copy packed B fragments (once per block) ----
    {
        const uint4* src = reinterpret_cast<const uint4*>(Bp);
        uint4* dst = reinterpret_cast<uint4*>(Bs);
        for (int i = tid; i < BP_SZ / 4; i += 256) dst[i] = src[i];
    }
    __syncthreads();

#pragma unroll
    for (int mc = 0; mc < 4; mc++) {       // 4 chunks of 32 nodes
        float acc[NTW][4];
#pragma unroll
        for (int t = 0; t < NTW; t++)
#pragma unroll
            for (int q = 0; q < 4; q++) acc[t][q] = 0.f;

#pragma unroll
        for (int ks = 0; ks < KS; ks++) {
            int r0 = mc * 32 + mg * 16 + g;
            int cbase = ks * 16 + tig * 2;
            unsigned int a0 = *reinterpret_cast<const unsigned int*>(&As[r0 * SA + cbase]);
            unsigned int a1 = *reinterpret_cast<const unsigned int*>(&As[(r0 + 8) * SA + cbase]);
            unsigned int a2 = *reinterpret_cast<const unsigned int*>(&As[r0 * SA + cbase + 8]);
            unsigned int a3 = *reinterpret_cast<const unsigned int*>(&As[(r0 + 8) * SA + cbase + 8]);
#pragma unroll
            for (int nt = 0; nt < NTW; nt++) {
                int gnt = ng * NTW + nt;
                uint2 bb = *reinterpret_cast<const uint2*>(
                    &Bs[((gnt * KS + ks) * 32 + lane) * 2]);
                asm volatile(
                    "mma.sync.aligned.m16n8k16.row.col.f32.f16.f16.f32 "
                    "{%0,%1,%2,%3}, {%4,%5,%6,%7}, {%8,%9}, {%0,%1,%2,%3};"
                    : "+f"(acc[nt][0]), "+f"(acc[nt][1]),
                      "+f"(acc[nt][2]), "+f"(acc[nt][3])
                    : "r"(a0), "r"(a1), "r"(a2), "r"(a3), "r"(bb.x), "r"(bb.y));
            }
        }

        // ---- epilogue: c0,c1 -> row g; c2,c3 -> row g+8 ----
        int n0 = nodeBase + mc * 32 + mg * 16 + g;
        int n1 = n0 + 8;
        bool v0 = n0 < N, v1 = n1 < N;
#pragma unroll
        for (int nt = 0; nt < NTW; nt++) {
            int gnt = ng * NTW + nt;
            int jbase = gnt * 8 + tig * 2;
            if (gnt * 8 < ZW) {
                __half2 h0 = __floats2half2_rn(acc[nt][0], acc[nt][1]);
                __half2 h1 = __floats2half2_rn(acc[nt][2], acc[nt][3]);
                if (v0) *reinterpret_cast<__half2*>(Z + (size_t)n0 * ZW + jbase) = h0;
                if (v1) *reinterpret_cast<__half2*>(Z + (size_t)n1 * ZW + jbase) = h1;
            } else {
                int co = jbase - ZW;
                float bx = bias[co], by = bias[co + 1];
                float2 w0 = make_float2(acc[nt][0] + bx, acc[nt][1] + by);
                float2 w1 = make_float2(acc[nt][2] + bx, acc[nt][3] + by);
                if (v0) *reinterpret_cast<float2*>(O + (size_t)n0 * COUT + co) = w0;
                if (v1) *reinterpret_cast<float2*>(O + (size_t)n1 * COUT + co) = w1;
            }
        }
    }
}

// smem sizes per instantiation
#define SM_6432 (128 * (64 + 8) * 2 + 10240 * 4 + 512)   // 59904
#define SM_3232 (128 * (32 + 8) * 2 + 5120 * 4 + 512)    // 31232
#define SM_3216 (128 * (32 + 8) * 2 + 2560 * 4 + 512)    // 20992
#define SM_1616 (128 * (16 + 8) * 2 + 1280 * 4 + 512)    // 11776

// ---------------------------------------------------------------------------
// Edge kernel: m_e = sum_k basis(pseudo_e)[k] * Z[src_e, k, :], RED into O[dst].
// ---------------------------------------------------------------------------
template <int COUT>
__global__ void edge_kernel(const int* __restrict__ src,
                            const int* __restrict__ dst,
                            const float* __restrict__ pseudo,
                            const __half* __restrict__ Z,
                            float* __restrict__ O, int E) {
    constexpr int TPE = COUT / 8;
    int tid = blockIdx.x * blockDim.x + threadIdx.x;
    int e = tid / TPE;
    int g = tid - e * TPE;
    if (e >= E) return;

    float t0 = __ldg(pseudo + 2 * e + 0);
    float t1 = __ldg(pseudo + 2 * e + 1);
    float a0 = 0.5f * (1.f - t0) * (1.f - t0);
    float a1 = -t0 * t0 + t0 + 0.5f;
    float a2 = 0.5f * t0 * t0;
    float c0 = 0.5f * (1.f - t1) * (1.f - t1);
    float c1 = -t1 * t1 + t1 + 0.5f;
    float c2 = 0.5f * t1 * t1;
    float b[9] = {a0 * c0, a0 * c1, a0 * c2,
                  a1 * c0, a1 * c1, a1 * c2,
                  a2 * c0, a2 * c1, a2 * c2};

    int s = __ldg(src + e);
    int d = __ldg(dst + e);
    const __half* zb = Z + (size_t)s * (9 * COUT) + g * 8;
    float4 acc0 = make_float4(0.f, 0.f, 0.f, 0.f);
    float4 acc1 = make_float4(0.f, 0.f, 0.f, 0.f);
#pragma unroll
    for (int k = 0; k < 9; k++) {
        float bk = b[k];
        uint4 raw = *reinterpret_cast<const uint4*>(zb + k * COUT);
        float2 f0 = __half22float2(*reinterpret_cast<const __half2*>(&raw.x));
        float2 f1 = __half22float2(*reinterpret_cast<const __half2*>(&raw.y));
        float2 f2 = __half22float2(*reinterpret_cast<const __half2*>(&raw.z));
        float2 f3 = __half22float2(*reinterpret_cast<const __half2*>(&raw.w));
        acc0.x = fmaf(bk, f0.x, acc0.x);
        acc0.y = fmaf(bk, f0.y, acc0.y);
        acc0.z = fmaf(bk, f1.x, acc0.z);
        acc0.w = fmaf(bk, f1.y, acc0.w);
        acc1.x = fmaf(bk, f2.x, acc1.x);
        acc1.y = fmaf(bk, f2.y, acc1.y);
        acc1.z = fmaf(bk, f3.x, acc1.z);
        acc1.w = fmaf(bk, f3.y, acc1.w);
    }
    float* o = O + (size_t)d * COUT + g * 8;
    asm volatile("red.global.add.v4.f32 [%0], {%1, %2, %3, %4};"
                 :: "l"(o), "f"(acc0.x), "f"(acc0.y), "f"(acc0.z), "f"(acc0.w)
                 : "memory");
    asm volatile("red.global.add.v4.f32 [%0], {%1, %2, %3, %4};"
                 :: "l"(o + 4), "f"(acc1.x), "f"(acc1.y), "f"(acc1.z), "f"(acc1.w)
                 : "memory");
}

__global__ void relu_copy4_kernel(const float4* __restrict__ in,
                                  float4* __restrict__ out, int n4) {
    int i = blockIdx.x * blockDim.x + threadIdx.x;
    if (i >= n4) return;
    float4 v = in[i];
    v.x = fmaxf(v.x, 0.f); v.y = fmaxf(v.y, 0.f);
    v.z = fmaxf(v.z, 0.f); v.w = fmaxf(v.w, 0.f);
    out[i] = v;
}

// ---------------------------------------------------------------------------
extern "C" void kernel_launch(void* const* d_in, const int* in_sizes, int n_in,
                              void* d_out, int out_size) {
    const float* x0      = (const float*)d_in[0];
    const int*   unpool1 = (const int*)d_in[1];
    const int*   edge1   = (const int*)d_in[2];
    const float* pseudo1 = (const float*)d_in[3];
    const float* skip1   = (const float*)d_in[4];
    const int*   unpool2 = (const int*)d_in[5];
    const int*   edge2   = (const int*)d_in[6];
    const float* pseudo2 = (const float*)d_in[7];
    const float* skip2   = (const float*)d_in[8];
    const float* W1a = (const float*)d_in[9];
    const float* R1a = (const float*)d_in[10];
    const float* b1a = (const float*)d_in[11];
    const float* W2a = (const float*)d_in[12];
    const float* R2a = (const float*)d_in[13];
    const float* b2a = (const float*)d_in[14];
    const float* W1b = (const float*)d_in[15];
    const float* R1b = (const float*)d_in[16];
    const float* b1b = (const float*)d_in[17];
    const float* W2b = (const float*)d_in[18];
    const float* R2b = (const float*)d_in[19];
    const float* b2b = (const float*)d_in[20];

    __half* ZP;
    float *bufA, *bufB;
    unsigned int* Bp;
    cudaGetSymbolAddress((void**)&ZP, g_Z);
    cudaGetSymbolAddress((void**)&bufA, g_bufA);
    cudaGetSymbolAddress((void**)&bufB, g_bufB);
    cudaGetSymbolAddress((void**)&Bp, g_Bp);

    // allow >48KB dynamic smem for the big instantiation
    cudaFuncSetAttribute(node_mma_kernel<64, 32>,
                         cudaFuncAttributeMaxDynamicSharedMemorySize, SM_6432);

    const int N1 = N1C, N2 = N2C, E1 = E1C, E2 = E2C;
    int g1 = (N1 + 127) / 128;   // 313
    int g2 = (N2 + 127) / 128;   // 1250

    // ---- pack all B fragments in one launch ----
    pack_all_kernel<<<(19200 + 255) / 256, 256>>>(W1a, R1a, W2a, R2a,
                                                  W1b, R1b, W2b, R2b, Bp);

    // ===================== Level 1: 64 -> 32 (N1, E1) =====================
    node_mma_kernel<64, 32><<<g1, 256, SM_6432>>>(x0, 64, nullptr, unpool1, 0,
                                                  Bp + BP_1A, b1a, ZP, bufA, N1);
    edge_kernel<32><<<(E1 * 4 + 255) / 256, 256>>>(edge1, edge1 + E1, pseudo1, ZP, bufA, E1);

    node_mma_kernel<64, 32><<<g1, 256, SM_6432>>>(bufA, 32, skip1, nullptr, 1,
                                                  Bp + BP_1A, b1a, ZP, bufB, N1);
    edge_kernel<32><<<(E1 * 4 + 255) / 256, 256>>>(edge1, edge1 + E1, pseudo1, ZP, bufB, E1);

    node_mma_kernel<32, 32><<<g1, 256, SM_3232>>>(bufB, 32, nullptr, nullptr, 1,
                                                  Bp + BP_2A, b2a, ZP, bufA, N1);
    edge_kernel<32><<<(E1 * 4 + 255) / 256, 256>>>(edge1, edge1 + E1, pseudo1, ZP, bufA, E1);
    // bufA = h1 (pre-relu; relu applied at gather below)

    // ===================== Level 2: 32 -> 16 (N2, E2) =====================
    node_mma_kernel<32, 16><<<g2, 256, SM_3216>>>(bufA, 32, nullptr, unpool2, 1,
                                                  Bp + BP_1B, b1b, ZP, bufB, N2);
    edge_kernel<16><<<(E2 * 2 + 255) / 256, 256>>>(edge2, edge2 + E2, pseudo2, ZP, bufB, E2);

    node_mma_kernel<32, 16><<<g2, 256, SM_3216>>>(bufB, 16, skip2, nullptr, 1,
                                                  Bp + BP_1B, b1b, ZP, bufA, N2);
    edge_kernel<16><<<(E2 * 2 + 255) / 256, 256>>>(edge2, edge2 + E2, pseudo2, ZP, bufA, E2);

    node_mma_kernel<16, 16><<<g2, 256, SM_1616>>>(bufA, 16, nullptr, nullptr, 1,
                                                  Bp + BP_2B, b2b, ZP, bufB, N2);
    edge_kernel<16><<<(E2 * 2 + 255) / 256, 256>>>(edge2, edge2 + E2, pseudo2, ZP, bufB, E2);

    // final relu -> output
    int n4 = N2 * 16 / 4;
    relu_copy4_kernel<<<(n4 + 255) / 256, 256>>>((const float4*)bufB,
                                                 (float4*)d_out, n4);
}

// round 8
// speedup vs baseline: 1.0794x; 1.0794x over previous
#include <cuda_runtime.h>
#include <cuda_fp16.h>
#include <cstdint>

// Problem constants (fixed by the dataset)
#define N0C 10000
#define N1C 40000
#define N2C 160000
#define E1C 240000
#define E2C 960000

// Static scratch (no allocation allowed)
__device__ __half g_Z[N2C * 9 * 16];               // 46.1 MB (>= N1C*9*32 halves)
__device__ float g_bufA[N2C * 32];                 // 20.5 MB
__device__ float g_bufB[N2C * 32];                 // 20.5 MB
// B-operand packed in exact mma.m16n8k16 fragment order (uint32 = 2 halves)
__device__ unsigned int g_Bp[19200];
#define BP_1A 0        // 320/8 * 4ks * 64 = 10240
#define BP_2A 10240    // 320/8 * 2ks * 64 = 5120
#define BP_1B 15360    // 160/8 * 2ks * 64 = 2560
#define BP_2B 17920    // 160/8 * 1ks * 64 = 1280

// ===========================================================================
// Pack B fragments: Wt[j][k] (j = output col of [W|R] concat, k = input chan)
//   j  = nt*8 + (lane>>2)
//   kb = ks*16 + (lane&3)*2 + r*8   -> halves (kb, kb+1)
// ===========================================================================
__device__ __forceinline__ float wt_val(const float* __restrict__ W,
                                        const float* __restrict__ R,
                                        int CIN, int COUT, int j, int k) {
    if (j < 9 * COUT) {
        int kk = j / COUT;
        int co = j - kk * COUT;
        return W[((size_t)kk * CIN + k) * COUT + co];
    }
    return R[(size_t)k * COUT + (j - 9 * COUT)];
}

__device__ __forceinline__ void pack_b_one(const float* __restrict__ W,
                                           const float* __restrict__ R,
                                           int CIN, int COUT,
                                           unsigned int* __restrict__ Bp, int u) {
    int r = u & 1;
    int lane = (u >> 1) & 31;
    int rest = u >> 6;
    int KS = CIN / 16;
    int ks = rest % KS;
    int nt = rest / KS;
    int j = nt * 8 + (lane >> 2);
    int kb = ks * 16 + (lane & 3) * 2 + r * 8;
    __half2 h = __floats2half2_rn(wt_val(W, R, CIN, COUT, j, kb),
                                  wt_val(W, R, CIN, COUT, j, kb + 1));
    Bp[u] = *reinterpret_cast<unsigned int*>(&h);
}

__global__ void pack_all_kernel(const float* W1a, const float* R1a,
                                const float* W2a, const float* R2a,
                                const float* W1b, const float* R1b,
                                const float* W2b, const float* R2b,
                                unsigned int* __restrict__ Bp) {
    int i = blockIdx.x * blockDim.x + threadIdx.x;
    if (i < 10240)       pack_b_one(W1a, R1a, 64, 32, Bp + BP_1A, i);
    else if (i < 15360)  pack_b_one(W2a, R2a, 32, 32, Bp + BP_2A, i - 10240);
    else if (i < 17920)  pack_b_one(W1b, R1b, 32, 16, Bp + BP_1B, i - 15360);
    else if (i < 19200)  pack_b_one(W2b, R2b, 16, 16, Bp + BP_2B, i - 17920);
}

// ===========================================================================
// Warp-autonomous HMMA node kernel: NO smem, NO barriers.
// 256 threads = 8 warps (2 M-groups x 4 N-groups), 32 nodes/block.
// A frags gathered directly from global as float2 -> half2 (cols are
// 16-aligned-region uniform since CA is a multiple of 16).
// B frags __ldg'd from packed L2-resident image.
//   Z[n, 0:9*COUT] (fp16) = X[n,:] @ Wcat ; O[n,:] = X[n,:] @ R + b (fp32)
// ===========================================================================
template <int CIN, int COUT>
__device__ __forceinline__ unsigned int ldcvt(const float* __restrict__ xA, int CA,
                                              const float* __restrict__ xB,
                                              int reluA, int r, int c) {
    float2 v;
    if (c < CA) {
        v = __ldg(reinterpret_cast<const float2*>(xA + (size_t)r * CA + c));
        if (reluA) { v.x = fmaxf(v.x, 0.f); v.y = fmaxf(v.y, 0.f); }
    } else {
        v = __ldg(reinterpret_cast<const float2*>(xB + (size_t)r * (CIN - CA) + (c - CA)));
    }
    __half2 h = __floats2half2_rn(v.x, v.y);
    return *reinterpret_cast<unsigned int*>(&h);
}

template <int CIN, int COUT>
__global__ void __launch_bounds__(256)
node_mma_kernel(const float* __restrict__ xA, int CA,
                const float* __restrict__ xB,
                const int* __restrict__ gidx, int reluA,
                const unsigned int* __restrict__ Bp,
                const float* __restrict__ bias,
                __half* __restrict__ Z, float* __restrict__ O) {
    constexpr int KS = CIN / 16;
    constexpr int NT_TOT = 10 * COUT / 8;
    constexpr int NTW = NT_TOT / 4;        // tiles per warp (10 or 5)
    constexpr int ZW = 9 * COUT;

    int tid = threadIdx.x;
    int lane = tid & 31;
    int wid = tid >> 5;
    int mg = wid >> 2;                     // 0..1 M group
    int ng = wid & 3;                      // 0..3 N group
    int g = lane >> 2;                     // 0..7
    int tig = lane & 3;                    // 0..3
    int nodeBase = blockIdx.x * 32;

    int n0 = nodeBase + mg * 16 + g;
    int n1 = n0 + 8;
    int r0 = gidx ? __ldg(gidx + n0) : n0;
    int r1 = gidx ? __ldg(gidx + n1) : n1;

    float acc[NTW][4];
#pragma unroll
    for (int t = 0; t < NTW; t++)
#pragma unroll
        for (int q = 0; q < 4; q++) acc[t][q] = 0.f;

#pragma unroll
    for (int ks = 0; ks < KS; ks++) {
        int cb = ks * 16 + tig * 2;
        unsigned int a0 = ldcvt<CIN, COUT>(xA, CA, xB, reluA, r0, cb);
        unsigned int a1 = ldcvt<CIN, COUT>(xA, CA, xB, reluA, r1, cb);
        unsigned int a2 = ldcvt<CIN, COUT>(xA, CA, xB, reluA, r0, cb + 8);
        unsigned int a3 = ldcvt<CIN, COUT>(xA, CA, xB, reluA, r1, cb + 8);
#pragma unroll
        for (int nt = 0; nt < NTW; nt++) {
            int gnt = ng * NTW + nt;
            uint2 bb = __ldg(reinterpret_cast<const uint2*>(
                &Bp[((gnt * KS + ks) * 32 + lane) * 2]));
            asm volatile(
                "mma.sync.aligned.m16n8k16.row.col.f32.f16.f16.f32 "
                "{%0,%1,%2,%3}, {%4,%5,%6,%7}, {%8,%9}, {%0,%1,%2,%3};"
                : "+f"(acc[nt][0]), "+f"(acc[nt][1]),
                  "+f"(acc[nt][2]), "+f"(acc[nt][3])
                : "r"(a0), "r"(a1), "r"(a2), "r"(a3), "r"(bb.x), "r"(bb.y));
        }
    }

    // ---- epilogue: c0,c1 -> row g (n0); c2,c3 -> row g+8 (n1) ----
#pragma unroll
    for (int nt = 0; nt < NTW; nt++) {
        int gnt = ng * NTW + nt;
        int jbase = gnt * 8 + tig * 2;
        if (gnt * 8 < ZW) {
            __half2 h0 = __floats2half2_rn(acc[nt][0], acc[nt][1]);
            __half2 h1 = __floats2half2_rn(acc[nt][2], acc[nt][3]);
            *reinterpret_cast<__half2*>(Z + (size_t)n0 * ZW + jbase) = h0;
            *reinterpret_cast<__half2*>(Z + (size_t)n1 * ZW + jbase) = h1;
        } else {
            int co = jbase - ZW;
            float bx = __ldg(bias + co), by = __ldg(bias + co + 1);
            float2 w0 = make_float2(acc[nt][0] + bx, acc[nt][1] + by);
            float2 w1 = make_float2(acc[nt][2] + bx, acc[nt][3] + by);
            *reinterpret_cast<float2*>(O + (size_t)n0 * COUT + co) = w0;
            *reinterpret_cast<float2*>(O + (size_t)n1 * COUT + co) = w1;
        }
    }
}

// ---------------------------------------------------------------------------
// Edge kernel: m_e = sum_k basis(pseudo_e)[k] * Z[src_e, k, :], RED into O[dst].
// ---------------------------------------------------------------------------
template <int COUT>
__global__ void edge_kernel(const int* __restrict__ src,
                            const int* __restrict__ dst,
                            const float* __restrict__ pseudo,
                            const __half* __restrict__ Z,
                            float* __restrict__ O, int E) {
    constexpr int TPE = COUT / 8;
    int tid = blockIdx.x * blockDim.x + threadIdx.x;
    int e = tid / TPE;
    int g = tid - e * TPE;
    if (e >= E) return;

    float t0 = __ldg(pseudo + 2 * e + 0);
    float t1 = __ldg(pseudo + 2 * e + 1);
    float a0 = 0.5f * (1.f - t0) * (1.f - t0);
    float a1 = -t0 * t0 + t0 + 0.5f;
    float a2 = 0.5f * t0 * t0;
    float c0 = 0.5f * (1.f - t1) * (1.f - t1);
    float c1 = -t1 * t1 + t1 + 0.5f;
    float c2 = 0.5f * t1 * t1;
    float b[9] = {a0 * c0, a0 * c1, a0 * c2,
                  a1 * c0, a1 * c1, a1 * c2,
                  a2 * c0, a2 * c1, a2 * c2};

    int s = __ldg(src + e);
    int d = __ldg(dst + e);
    const __half* zb = Z + (size_t)s * (9 * COUT) + g * 8;
    float4 acc0 = make_float4(0.f, 0.f, 0.f, 0.f);
    float4 acc1 = make_float4(0.f, 0.f, 0.f, 0.f);
#pragma unroll
    for (int k = 0; k < 9; k++) {
        float bk = b[k];
        uint4 raw = *reinterpret_cast<const uint4*>(zb + k * COUT);
        float2 f0 = __half22float2(*reinterpret_cast<const __half2*>(&raw.x));
        float2 f1 = __half22float2(*reinterpret_cast<const __half2*>(&raw.y));
        float2 f2 = __half22float2(*reinterpret_cast<const __half2*>(&raw.z));
        float2 f3 = __half22float2(*reinterpret_cast<const __half2*>(&raw.w));
        acc0.x = fmaf(bk, f0.x, acc0.x);
        acc0.y = fmaf(bk, f0.y, acc0.y);
        acc0.z = fmaf(bk, f1.x, acc0.z);
        acc0.w = fmaf(bk, f1.y, acc0.w);
        acc1.x = fmaf(bk, f2.x, acc1.x);
        acc1.y = fmaf(bk, f2.y, acc1.y);
        acc1.z = fmaf(bk, f3.x, acc1.z);
        acc1.w = fmaf(bk, f3.y, acc1.w);
    }
    float* o = O + (size_t)d * COUT + g * 8;
    asm volatile("red.global.add.v4.f32 [%0], {%1, %2, %3, %4};"
                 :: "l"(o), "f"(acc0.x), "f"(acc0.y), "f"(acc0.z), "f"(acc0.w)
                 : "memory");
    asm volatile("red.global.add.v4.f32 [%0], {%1, %2, %3, %4};"
                 :: "l"(o + 4), "f"(acc1.x), "f"(acc1.y), "f"(acc1.z), "f"(acc1.w)
                 : "memory");
}

__global__ void relu_copy4_kernel(const float4* __restrict__ in,
                                  float4* __restrict__ out, int n4) {
    int i = blockIdx.x * blockDim.x + threadIdx.x;
    if (i >= n4) return;
    float4 v = in[i];
    v.x = fmaxf(v.x, 0.f); v.y = fmaxf(v.y, 0.f);
    v.z = fmaxf(v.z, 0.f); v.w = fmaxf(v.w, 0.f);
    out[i] = v;
}

// ---------------------------------------------------------------------------
extern "C" void kernel_launch(void* const* d_in, const int* in_sizes, int n_in,
                              void* d_out, int out_size) {
    const float* x0      = (const float*)d_in[0];
    const int*   unpool1 = (const int*)d_in[1];
    const int*   edge1   = (const int*)d_in[2];
    const float* pseudo1 = (const float*)d_in[3];
    const float* skip1   = (const float*)d_in[4];
    const int*   unpool2 = (const int*)d_in[5];
    const int*   edge2   = (const int*)d_in[6];
    const float* pseudo2 = (const float*)d_in[7];
    const float* skip2   = (const float*)d_in[8];
    const float* W1a = (const float*)d_in[9];
    const float* R1a = (const float*)d_in[10];
    const float* b1a = (const float*)d_in[11];
    const float* W2a = (const float*)d_in[12];
    const float* R2a = (const float*)d_in[13];
    const float* b2a = (const float*)d_in[14];
    const float* W1b = (const float*)d_in[15];
    const float* R1b = (const float*)d_in[16];
    const float* b1b = (const float*)d_in[17];
    const float* W2b = (const float*)d_in[18];
    const float* R2b = (const float*)d_in[19];
    const float* b2b = (const float*)d_in[20];

    __half* ZP;
    float *bufA, *bufB;
    unsigned int* Bp;
    cudaGetSymbolAddress((void**)&ZP, g_Z);
    cudaGetSymbolAddress((void**)&bufA, g_bufA);
    cudaGetSymbolAddress((void**)&bufB, g_bufB);
    cudaGetSymbolAddress((void**)&Bp, g_Bp);

    const int N1 = N1C, N2 = N2C, E1 = E1C, E2 = E2C;

    // ---- pack all B fragments in one launch ----
    pack_all_kernel<<<(19200 + 255) / 256, 256>>>(W1a, R1a, W2a, R2a,
                                                  W1b, R1b, W2b, R2b, Bp);

    // ===================== Level 1: 64 -> 32 (N1, E1) =====================
    node_mma_kernel<64, 32><<<N1 / 32, 256>>>(x0, 64, nullptr, unpool1, 0,
                                              Bp + BP_1A, b1a, ZP, bufA);
    edge_kernel<32><<<(E1 * 4 + 255) / 256, 256>>>(edge1, edge1 + E1, pseudo1, ZP, bufA, E1);

    node_mma_kernel<64, 32><<<N1 / 32, 256>>>(bufA, 32, skip1, nullptr, 1,
                                              Bp + BP_1A, b1a, ZP, bufB);
    edge_kernel<32><<<(E1 * 4 + 255) / 256, 256>>>(edge1, edge1 + E1, pseudo1, ZP, bufB, E1);

    node_mma_kernel<32, 32><<<N1 / 32, 256>>>(bufB, 32, nullptr, nullptr, 1,
                                              Bp + BP_2A, b2a, ZP, bufA);
    edge_kernel<32><<<(E1 * 4 + 255) / 256, 256>>>(edge1, edge1 + E1, pseudo1, ZP, bufA, E1);
    // bufA = h1 (pre-relu; relu applied at gather below)

    // ===================== Level 2: 32 -> 16 (N2, E2) =====================
    node_mma_kernel<32, 16><<<N2 / 32, 256>>>(bufA, 32, nullptr, unpool2, 1,
                                              Bp + BP_1B, b1b, ZP, bufB);
    edge_kernel<16><<<(E2 * 2 + 255) / 256, 256>>>(edge2, edge2 + E2, pseudo2, ZP, bufB, E2);

    node_mma_kernel<32, 16><<<N2 / 32, 256>>>(bufB, 16, skip2, nullptr, 1,
                                              Bp + BP_1B, b1b, ZP, bufA);
    edge_kernel<16><<<(E2 * 2 + 255) / 256, 256>>>(edge2, edge2 + E2, pseudo2, ZP, bufA, E2);

    node_mma_kernel<16, 16><<<N2 / 32, 256>>>(bufA, 16, nullptr, nullptr, 1,
                                              Bp + BP_2B, b2b, ZP, bufB);
    edge_kernel<16><<<(E2 * 2 + 255) / 256, 256>>>(edge2, edge2 + E2, pseudo2, ZP, bufB, E2);

    // final relu -> output
    int n4 = N2 * 16 / 4;
    relu_copy4_kernel<<<(n4 + 255) / 256, 256>>>((const float4*)bufB,
                                                 (float4*)d_out, n4);
}